// round 14
// baseline (speedup 1.0000x reference)
#include <cuda_runtime.h>

#define HH 8192
#define W  512
#define NPIX (HH * W)

// Union-find over priority keys: key = idx (strong) or idx + MOD (weak).
// Min-attachment => root is strong iff component contains a strong pixel.
__device__ unsigned char g_mask[NPIX];   // bit0 = weak, bit1 = strong
__device__ int           g_nstat[NPIX];  // parent KEY per weak pixel

template <int MOD>
__device__ __forceinline__ int uf_find(int* p, int key) {
    int curr = p[key & (MOD - 1)];
    if (curr != key) {
        int prev = key & (MOD - 1), next;
        while (curr > (next = p[curr & (MOD - 1)])) {
            p[prev] = next;                 // path halving
            prev = curr & (MOD - 1);
            curr = next;
        }
    }
    return curr;
}

template <int MOD>
__device__ __forceinline__ void uf_union(int* p, int ka, int kb) {
    int va = uf_find<MOD>(p, ka);
    int vb = uf_find<MOD>(p, kb);
    bool rep;
    do {
        rep = false;
        if (va != vb) {
            int ret;
            if (va < vb) {
                if ((ret = atomicCAS(&p[vb & (MOD - 1)], vb, va)) != vb) { vb = ret; rep = true; }
            } else {
                if ((ret = atomicCAS(&p[va & (MOD - 1)], va, vb)) != va) { va = ret; rep = true; }
            }
        }
    } while (rep);
}

// exact uint8 convert: input in [-1,1) => result in [0,255], no clamp needed
__device__ __forceinline__ unsigned int cv(float v) {
    return (unsigned int)(int)floorf((v + 1.0f) * 0.5f * 255.0f);
}

// phase 2: Sobel + argmax + direction on the 34x34 mag region (rows 0..33)
template <bool CHK>
__device__ __forceinline__ void phase2(const unsigned int (*spack)[40], int* smag,
                                       unsigned char* sdir, int y0, int x0, int tid) {
    for (int i = tid; i < 34 * 34; i += 256) {
        int my = i / 34, mx = i - my * 34;
        int mag = 0, dir = 0;
        bool ok = true;
        if (CHK) {
            int yy = y0 - 1 + my, xx = x0 - 1 + mx;
            ok = (yy >= 0 && yy < HH && xx >= 0 && xx < W);
        }
        if (ok) {
            const unsigned int* r0 = &spack[my    ][mx + 2];
            const unsigned int* r1 = &spack[my + 1][mx + 2];
            const unsigned int* r2 = &spack[my + 2][mx + 2];
            unsigned int nmm = r0[0], nm0 = r0[1], nmp = r0[2];
            unsigned int n0m = r1[0],               n0p = r1[2];
            unsigned int npm = r2[0], np0 = r2[1], npp = r2[2];
            unsigned int Px = nmp + 2u * n0p + npp;   // fields <= 1020 < 1024
            unsigned int Mx = nmm + 2u * n0m + npm;
            unsigned int Py = npm + 2u * np0 + npp;
            unsigned int My = nmm + 2u * nm0 + nmp;
            int g0x = (int)(Px & 1023u)         - (int)(Mx & 1023u);
            int g0y = (int)(Py & 1023u)         - (int)(My & 1023u);
            int g1x = (int)((Px >> 10) & 1023u) - (int)((Mx >> 10) & 1023u);
            int g1y = (int)((Py >> 10) & 1023u) - (int)((My >> 10) & 1023u);
            int g2x = (int)(Px >> 20)           - (int)(Mx >> 20);
            int g2y = (int)(Py >> 20)           - (int)(My >> 20);
            int m0 = abs(g0x) + abs(g0y);
            int m1 = abs(g1x) + abs(g1y);
            int m2 = abs(g2x) + abs(g2y);
            int bm = max(m0, max(m1, m2));
            int bgx = (m0 == bm) ? g0x : (m1 == bm) ? g1x : g2x;  // first-max
            int bgy = (m0 == bm) ? g0y : (m1 == bm) ? g1y : g2y;
            mag = bm;
            const float TG22 = 0.4142135623730951f;
            float ax = (float)abs(bgx), ay = (float)abs(bgy);     // exact
            if (ay < TG22 * ax)      dir = 0;
            else if (ay * TG22 > ax) dir = 1;
            else dir = (bgx * bgy >= 0) ? 2 : 3;
        }
        smag[my * 36 + mx] = mag;
        sdir[my * 36 + mx] = (unsigned char)dir;
    }
}

// ---------------------------------------------------------------------------
// K1: convert+pack (vectorized fast path) + Sobel + argmax + NMS + local CC
//     32x32 tile, ~17KB smem => 8 blocks/SM (threads-bound), occ ~90%
// ---------------------------------------------------------------------------
__global__ void __launch_bounds__(256) k_grad(const float* __restrict__ in) {
    __shared__ __align__(16) unsigned int spack[36][40];  // col j => gx = x0-4+j
    __shared__ int           smag[34 * 36];
    __shared__ unsigned char sdir[34 * 36];
    __shared__ int           spar[1024];
    __shared__ unsigned char smsk[1024];

    const int bx = blockIdx.x, by = blockIdx.y;
    const int y0 = by * 32, x0 = bx * 32;
    const int tid = threadIdx.x;

    if (bx >= 1 && bx <= 14) {
        // fast path: 36 rows x 10 float4 slots covering gx = x0-4 .. x0+35
        for (int s = tid; s < 36 * 10; s += 256) {
            int row = s / 10, v = s - row * 10;
            int gy = y0 - 2 + row;
            gy = max(0, min(HH - 1, gy));
            int b = gy >> 9, h = gy & 511;
            int gxb = x0 - 4 + v * 4;                 // 16B aligned, in-range
            const float4* p = reinterpret_cast<const float4*>(
                in + ((b * 3) << 18) + (h << 9) + gxb);
            float4 cr = p[0];
            float4 cg = p[1 << 16];                   // + (1<<18) floats
            float4 cb = p[2 << 16];
            uint4 st;
            st.x = cv(cr.x) | (cv(cg.x) << 10) | (cv(cb.x) << 20);
            st.y = cv(cr.y) | (cv(cg.y) << 10) | (cv(cb.y) << 20);
            st.z = cv(cr.z) | (cv(cg.z) << 10) | (cv(cb.z) << 20);
            st.w = cv(cr.w) | (cv(cg.w) << 10) | (cv(cb.w) << 20);
            *reinterpret_cast<uint4*>(&spack[row][v * 4]) = st;
        }
    } else {
        // scalar path (x-edge blocks): fill cols j=2..37 with clamped loads
        for (int i = tid; i < 36 * 36; i += 256) {
            int row = i / 36, col = i - row * 36;
            int gy = y0 - 2 + row; gy = max(0, min(HH - 1, gy));
            int gx = x0 - 2 + col; gx = max(0, min(W - 1, gx));
            int b = gy >> 9, h = gy & 511;
            int base = ((b * 3) << 18) + (h << 9) + gx;
            spack[row][col + 2] = cv(in[base])
                                | (cv(in[base + (1 << 18)]) << 10)
                                | (cv(in[base + (2 << 18)]) << 20);
        }
    }
    __syncthreads();

    if (bx >= 1 && bx <= 14 && by >= 1 && by <= 254)
        phase2<false>(spack, smag, sdir, y0, x0, tid);
    else
        phase2<true>(spack, smag, sdir, y0, x0, tid);
    __syncthreads();

    // NMS + thresholds (branch-free neighbor offsets)
    for (int i = tid; i < 1024; i += 256) {
        int oy = i >> 5, ox = i & 31;
        int cen = (oy + 1) * 36 + (ox + 1);
        int m = smag[cen];
        int d = sdir[cen];
        int o1 = (d == 0) ? -1 : (d == 1) ? -36 : (d == 2) ? -37 : -35;
        int n1 = smag[cen + o1], n2 = smag[cen - o1];
        bool keep = (m > n1) && (m >= n2);
        unsigned char msk = 0;
        if (keep && m > 100) msk = 1;
        if (keep && m > 200) msk = 3;
        smsk[i] = msk;
        spar[i] = (msk & 2) ? i : i + 1024;   // key: strong in low range
    }
    __syncthreads();

    // local union-find inside the tile (smem atomics, key-encoded)
    for (int i = tid; i < 1024; i += 256) {
        if (smsk[i] & 1) {
            int ki = (smsk[i] & 2) ? i : i + 1024;
            int ly = i >> 5, lx = i & 31;
            if (lx < 31 && (smsk[i + 1] & 1))
                uf_union<1024>(spar, ki, (smsk[i + 1] & 2) ? i + 1 : i + 1025);
            if (ly < 31) {
                if (smsk[i + 32] & 1)
                    uf_union<1024>(spar, ki, (smsk[i + 32] & 2) ? i + 32 : i + 32 + 1024);
                if (lx > 0 && (smsk[i + 31] & 1))
                    uf_union<1024>(spar, ki, (smsk[i + 31] & 2) ? i + 31 : i + 31 + 1024);
                if (lx < 31 && (smsk[i + 33] & 1))
                    uf_union<1024>(spar, ki, (smsk[i + 33] & 2) ? i + 33 : i + 33 + 1024);
            }
        }
    }
    __syncthreads();

    // write mask; rooted global parent keys for weak pixels
    for (int i = tid; i < 1024; i += 256) {
        int oy = i >> 5, ox = i & 31;
        int gidx = (y0 + oy) * W + (x0 + ox);
        unsigned char msk = smsk[i];
        g_mask[gidx] = msk;
        if (msk & 1) {
            int lkey = (msk & 2) ? i : i + 1024;
            int r = uf_find<1024>(spar, lkey);
            int li = r & 1023;
            int gr = (y0 + (li >> 5)) * W + (x0 + (li & 31));
            g_nstat[gidx] = (r < 1024) ? gr : gr + NPIX;   // preserve strongness
        }
    }
}

// ---------------------------------------------------------------------------
// K2: cross-tile boundary unions (global atomics, key-encoded), 32x32 tiles
// ---------------------------------------------------------------------------
#define NB_BOT (256 * 512)
#define NB_COL (8192 * 16)

__device__ __forceinline__ int gkey(int idx, unsigned char m) {
    return (m & 2) ? idx : idx + NPIX;
}

__global__ void __launch_bounds__(256) k_union() {
    int t = blockIdx.x * 256 + threadIdx.x;
    if (t < NB_BOT) {
        int x = t & 511, ty = t >> 9;
        int y = ty * 32 + 31;
        if (y >= HH - 1) return;
        int idx = y * W + x;
        unsigned char mi = g_mask[idx];
        if (!(mi & 1)) return;
        int ki = gkey(idx, mi);
        int s = idx + W;
        unsigned char ms = g_mask[s];
        if (ms & 1) uf_union<NPIX>(g_nstat, ki, gkey(s, ms));
        if (x > 0) {
            unsigned char mw = g_mask[s - 1];
            if (mw & 1) uf_union<NPIX>(g_nstat, ki, gkey(s - 1, mw));
        }
        if (x < W - 1) {
            unsigned char me = g_mask[s + 1];
            if (me & 1) uf_union<NPIX>(g_nstat, ki, gkey(s + 1, me));
        }
    } else if (t < NB_BOT + NB_COL) {
        int t2 = t - NB_BOT;
        int y = t2 >> 4, tx = t2 & 15;
        int x = tx * 32 + 31;
        if (x >= W - 1) return;
        int idx = y * W + x;
        unsigned char mi = g_mask[idx];
        if (!(mi & 1)) return;
        int ki = gkey(idx, mi);
        unsigned char me = g_mask[idx + 1];
        if (me & 1) uf_union<NPIX>(g_nstat, ki, gkey(idx + 1, me));
        if ((y & 31) != 31 && y < HH - 1) {
            unsigned char md = g_mask[idx + W + 1];
            if (md & 1) uf_union<NPIX>(g_nstat, ki, gkey(idx + W + 1, md));
        }
    } else {
        int t3 = t - NB_BOT - NB_COL;
        if (t3 >= NB_COL) return;
        int y = t3 >> 4, tx = t3 & 15;
        int x = tx * 32;
        if (x == 0 || (y & 31) == 31 || y >= HH - 1) return;
        int idx = y * W + x;
        unsigned char mi = g_mask[idx];
        if (!(mi & 1)) return;
        unsigned char md = g_mask[idx + W - 1];
        if (md & 1) uf_union<NPIX>(g_nstat, gkey(idx, mi), gkey(idx + W - 1, md));
    }
}

// ---------------------------------------------------------------------------
// K3: find root per weak pixel; edge iff root key < NPIX (strong root)
// ---------------------------------------------------------------------------
__global__ void __launch_bounds__(256) k_out(float* __restrict__ out) {
    int t = blockIdx.x * 256 + threadIdx.x;
    int idx8 = t << 3;
    if (idx8 >= NPIX) return;
    uint2 m8 = *(const uint2*)(g_mask + idx8);
    unsigned int mw[2] = { m8.x, m8.y };
    unsigned int m[8];
    #pragma unroll
    for (int j = 0; j < 8; j++) m[j] = (mw[j >> 2] >> (8 * (j & 3))) & 0xFFu;

    // wave 1: independent first-hop parent loads (weak-only pixels)
    int par[8];
    #pragma unroll
    for (int j = 0; j < 8; j++)
        par[j] = (m[j] == 1u) ? g_nstat[idx8 + j] : -1;

    float v[8];
    #pragma unroll
    for (int j = 0; j < 8; j++) {
        float val = -1.0f;
        if (m[j] & 2u) {
            val = 1.0f;                         // strong => edge
        } else if (m[j] & 1u) {
            int idx = idx8 + j;
            int curr = par[j];
            int key = idx + NPIX;
            if (curr != key) {
                int prev = idx, next;
                while (curr > (next = g_nstat[curr & (NPIX - 1)])) {
                    g_nstat[prev] = next;       // halving: cooperate with peers
                    prev = curr & (NPIX - 1);
                    curr = next;
                }
            }
            if (curr < NPIX) val = 1.0f;        // strong-rooted component
        }
        v[j] = val;
    }

    int y = idx8 >> 9, x = idx8 & 511;
    int b = y >> 9, hh = y & 511;
    int o = ((b * 3) << 18) + (hh << 9) + x;
    float4 lo = make_float4(v[0], v[1], v[2], v[3]);
    float4 hi = make_float4(v[4], v[5], v[6], v[7]);
    float4* o4 = (float4*)out;
    int q = o >> 2;
    o4[q]             = lo;  o4[q + 1]             = hi;
    o4[q + (1 << 16)] = lo;  o4[q + (1 << 16) + 1] = hi;
    o4[q + (2 << 16)] = lo;  o4[q + (2 << 16) + 1] = hi;
}

extern "C" void kernel_launch(void* const* d_in, const int* in_sizes, int n_in,
                              void* d_out, int out_size) {
    const float* x = (const float*)d_in[0];
    float* out = (float*)d_out;
    dim3 g1(16, 256);
    k_grad<<<g1, 256>>>(x);
    k_union<<<(NB_BOT + 2 * NB_COL) / 256, 256>>>();
    k_out<<<NPIX / 2048, 256>>>(out);
}

// round 15
// speedup vs baseline: 1.0587x; 1.0587x over previous
#include <cuda_runtime.h>

#define HH 8192
#define W  512
#define NPIX (HH * W)

// Union-find over priority keys: key = idx (strong) or idx + MOD (weak).
// Min-attachment => root is strong iff component contains a strong pixel.
__device__ unsigned char g_mask[NPIX];   // bit0 = weak, bit1 = strong
__device__ int           g_nstat[NPIX];  // parent KEY per weak pixel

template <int MOD>
__device__ __forceinline__ int uf_find(int* p, int key) {
    int curr = p[key & (MOD - 1)];
    if (curr != key) {
        int prev = key & (MOD - 1), next;
        while (curr > (next = p[curr & (MOD - 1)])) {
            p[prev] = next;                 // path halving
            prev = curr & (MOD - 1);
            curr = next;
        }
    }
    return curr;
}

template <int MOD>
__device__ __forceinline__ void uf_union(int* p, int ka, int kb) {
    int va = uf_find<MOD>(p, ka);
    int vb = uf_find<MOD>(p, kb);
    bool rep;
    do {
        rep = false;
        if (va != vb) {
            int ret;
            if (va < vb) {
                if ((ret = atomicCAS(&p[vb & (MOD - 1)], vb, va)) != vb) { vb = ret; rep = true; }
            } else {
                if ((ret = atomicCAS(&p[va & (MOD - 1)], va, vb)) != va) { va = ret; rep = true; }
            }
        }
    } while (rep);
}

// exact uint8 convert: input in [-1,1) => result in [0,255], no clamp needed
__device__ __forceinline__ unsigned int cv(float v) {
    return (unsigned int)(int)floorf((v + 1.0f) * 0.5f * 255.0f);
}

// per-pixel epilogue: unpack channel grads, argmax (first-max), direction
__device__ __forceinline__ void sobel_px(unsigned int Vp, unsigned int Vm,
                                         unsigned int Hb, unsigned int Ht,
                                         int* smag, unsigned char* sdir, int off) {
    int g0x = (int)(Vp & 1023u)         - (int)(Vm & 1023u);
    int g1x = (int)((Vp >> 10) & 1023u) - (int)((Vm >> 10) & 1023u);
    int g2x = (int)(Vp >> 20)           - (int)(Vm >> 20);
    int g0y = (int)(Hb & 1023u)         - (int)(Ht & 1023u);
    int g1y = (int)((Hb >> 10) & 1023u) - (int)((Ht >> 10) & 1023u);
    int g2y = (int)(Hb >> 20)           - (int)(Ht >> 20);
    int m0 = abs(g0x) + abs(g0y);
    int m1 = abs(g1x) + abs(g1y);
    int m2 = abs(g2x) + abs(g2y);
    int bm = max(m0, max(m1, m2));
    int bgx = (m0 == bm) ? g0x : (m1 == bm) ? g1x : g2x;  // first-max
    int bgy = (m0 == bm) ? g0y : (m1 == bm) ? g1y : g2y;
    const float TG22 = 0.4142135623730951f;
    float ax = (float)abs(bgx), ay = (float)abs(bgy);     // exact conversions
    int dir;
    if (ay < TG22 * ax)      dir = 0;
    else if (ay * TG22 > ax) dir = 1;
    else dir = (bgx * bgy >= 0) ? 2 : 3;
    smag[off] = bm;
    sdir[off] = (unsigned char)dir;
}

// generic (bounds-checked) phase 2 for edge blocks
__device__ __forceinline__ void phase2_chk(const unsigned int (*spack)[40], int* smag,
                                           unsigned char* sdir, int y0, int x0, int tid) {
    for (int i = tid; i < 34 * 34; i += 256) {
        int my = i / 34, mx = i - my * 34;
        int yy = y0 - 1 + my, xx = x0 - 1 + mx;
        if (yy >= 0 && yy < HH && xx >= 0 && xx < W) {
            const unsigned int* r0 = &spack[my    ][mx + 2];
            const unsigned int* r1 = &spack[my + 1][mx + 2];
            const unsigned int* r2 = &spack[my + 2][mx + 2];
            unsigned int Vm = r0[0] + 2u * r1[0] + r2[0];
            unsigned int Vp = r0[2] + 2u * r1[2] + r2[2];
            unsigned int Ht = r0[0] + 2u * r0[1] + r0[2];
            unsigned int Hb = r2[0] + 2u * r2[1] + r2[2];
            sobel_px(Vp, Vm, Hb, Ht, smag, sdir, my * 36 + mx);
        } else {
            smag[my * 36 + mx] = 0;
            sdir[my * 36 + mx] = 0;
        }
    }
}

// register-blocked phase 2 for interior blocks: lane = column, y-march,
// rolling registers: 3 LDS + ~10 packed adds per mag pixel
__device__ __forceinline__ void phase2_fast(const unsigned int (*spack)[40], int* smag,
                                            unsigned char* sdir, int tid) {
    int tx = tid & 31, ty = tid >> 5;                    // ty in 0..7
    int row0 = (ty < 2) ? ty * 5 : 10 + (ty - 2) * 4;    // rows: 5,5,4,4,4,4,4,4 (=34)
    int R    = (ty < 2) ? 5 : 4;
    int sx = tx + 2;                                     // spack cols sx..sx+2

    unsigned int c0t = spack[row0    ][sx], c1t = spack[row0    ][sx + 1], c2t = spack[row0    ][sx + 2];
    unsigned int c0m = spack[row0 + 1][sx], c1m = spack[row0 + 1][sx + 1], c2m = spack[row0 + 1][sx + 2];
    unsigned int h0 = c0t + 2u * c1t + c2t;
    unsigned int h1 = c0m + 2u * c1m + c2m;

    for (int r = 0; r < R; r++) {
        int my = row0 + r;
        unsigned int a0 = spack[my + 2][sx], a1 = spack[my + 2][sx + 1], a2 = spack[my + 2][sx + 2];
        unsigned int h2 = a0 + 2u * a1 + a2;
        unsigned int Vm = c0t + 2u * c0m + a0;
        unsigned int Vp = c2t + 2u * c2m + a2;
        sobel_px(Vp, Vm, h2, h0, smag, sdir, my * 36 + tx);
        c0t = c0m; c0m = a0; c2t = c2m; c2m = a2; h0 = h1; h1 = h2;
    }

    // leftover columns mx = 32, 33 (68 pixels) via generic path
    if (tid < 68) {
        int mx = 32 + (tid & 1);
        int my = tid >> 1;
        const unsigned int* r0 = &spack[my    ][mx + 2];
        const unsigned int* r1 = &spack[my + 1][mx + 2];
        const unsigned int* r2 = &spack[my + 2][mx + 2];
        unsigned int Vm = r0[0] + 2u * r1[0] + r2[0];
        unsigned int Vp = r0[2] + 2u * r1[2] + r2[2];
        unsigned int Ht = r0[0] + 2u * r0[1] + r0[2];
        unsigned int Hb = r2[0] + 2u * r2[1] + r2[2];
        sobel_px(Vp, Vm, Hb, Ht, smag, sdir, my * 36 + mx);
    }
}

// ---------------------------------------------------------------------------
// K1: convert+pack + Sobel (register-blocked) + argmax + NMS + local CC
//     32x32 tile, ~17KB smem, forced 8 blocks/SM
// ---------------------------------------------------------------------------
__global__ void __launch_bounds__(256, 8) k_grad(const float* __restrict__ in) {
    __shared__ __align__(16) unsigned int spack[36][40];  // col j => gx = x0-4+j
    __shared__ int           smag[34 * 36];
    __shared__ unsigned char sdir[34 * 36];
    __shared__ int           spar[1024];
    __shared__ unsigned char smsk[1024];

    const int bx = blockIdx.x, by = blockIdx.y;
    const int y0 = by * 32, x0 = bx * 32;
    const int tid = threadIdx.x;

    if (bx >= 1 && bx <= 14) {
        // fast path: 36 rows x 10 float4 slots covering gx = x0-4 .. x0+35
        for (int s = tid; s < 36 * 10; s += 256) {
            int row = s / 10, v = s - row * 10;
            int gy = y0 - 2 + row;
            gy = max(0, min(HH - 1, gy));
            int b = gy >> 9, h = gy & 511;
            int gxb = x0 - 4 + v * 4;                 // 16B aligned, in-range
            const float4* p = reinterpret_cast<const float4*>(
                in + ((b * 3) << 18) + (h << 9) + gxb);
            float4 cr = p[0];
            float4 cg = p[1 << 16];                   // + (1<<18) floats
            float4 cb = p[2 << 16];
            uint4 st;
            st.x = cv(cr.x) | (cv(cg.x) << 10) | (cv(cb.x) << 20);
            st.y = cv(cr.y) | (cv(cg.y) << 10) | (cv(cb.y) << 20);
            st.z = cv(cr.z) | (cv(cg.z) << 10) | (cv(cb.z) << 20);
            st.w = cv(cr.w) | (cv(cg.w) << 10) | (cv(cb.w) << 20);
            *reinterpret_cast<uint4*>(&spack[row][v * 4]) = st;
        }
    } else {
        // scalar path (x-edge blocks): fill cols j=2..37 with clamped loads
        for (int i = tid; i < 36 * 36; i += 256) {
            int row = i / 36, col = i - row * 36;
            int gy = y0 - 2 + row; gy = max(0, min(HH - 1, gy));
            int gx = x0 - 2 + col; gx = max(0, min(W - 1, gx));
            int b = gy >> 9, h = gy & 511;
            int base = ((b * 3) << 18) + (h << 9) + gx;
            spack[row][col + 2] = cv(in[base])
                                | (cv(in[base + (1 << 18)]) << 10)
                                | (cv(in[base + (2 << 18)]) << 20);
        }
    }
    __syncthreads();

    if (bx >= 1 && bx <= 14 && by >= 1 && by <= 254)
        phase2_fast(spack, smag, sdir, tid);
    else
        phase2_chk(spack, smag, sdir, y0, x0, tid);
    __syncthreads();

    // NMS + thresholds (branch-free neighbor offsets)
    for (int i = tid; i < 1024; i += 256) {
        int oy = i >> 5, ox = i & 31;
        int cen = (oy + 1) * 36 + (ox + 1);
        int m = smag[cen];
        int d = sdir[cen];
        int o1 = (d == 0) ? -1 : (d == 1) ? -36 : (d == 2) ? -37 : -35;
        int n1 = smag[cen + o1], n2 = smag[cen - o1];
        bool keep = (m > n1) && (m >= n2);
        unsigned char msk = 0;
        if (keep && m > 100) msk = 1;
        if (keep && m > 200) msk = 3;
        smsk[i] = msk;
        spar[i] = (msk & 2) ? i : i + 1024;   // key: strong in low range
    }
    __syncthreads();

    // local union-find inside the tile (smem atomics, key-encoded)
    for (int i = tid; i < 1024; i += 256) {
        if (smsk[i] & 1) {
            int ki = (smsk[i] & 2) ? i : i + 1024;
            int ly = i >> 5, lx = i & 31;
            if (lx < 31 && (smsk[i + 1] & 1))
                uf_union<1024>(spar, ki, (smsk[i + 1] & 2) ? i + 1 : i + 1025);
            if (ly < 31) {
                if (smsk[i + 32] & 1)
                    uf_union<1024>(spar, ki, (smsk[i + 32] & 2) ? i + 32 : i + 32 + 1024);
                if (lx > 0 && (smsk[i + 31] & 1))
                    uf_union<1024>(spar, ki, (smsk[i + 31] & 2) ? i + 31 : i + 31 + 1024);
                if (lx < 31 && (smsk[i + 33] & 1))
                    uf_union<1024>(spar, ki, (smsk[i + 33] & 2) ? i + 33 : i + 33 + 1024);
            }
        }
    }
    __syncthreads();

    // write mask; rooted global parent keys for weak pixels
    for (int i = tid; i < 1024; i += 256) {
        int oy = i >> 5, ox = i & 31;
        int gidx = (y0 + oy) * W + (x0 + ox);
        unsigned char msk = smsk[i];
        g_mask[gidx] = msk;
        if (msk & 1) {
            int lkey = (msk & 2) ? i : i + 1024;
            int r = uf_find<1024>(spar, lkey);
            int li = r & 1023;
            int gr = (y0 + (li >> 5)) * W + (x0 + (li & 31));
            g_nstat[gidx] = (r < 1024) ? gr : gr + NPIX;   // preserve strongness
        }
    }
}

// ---------------------------------------------------------------------------
// K2: cross-tile boundary unions (global atomics, key-encoded), 32x32 tiles
// ---------------------------------------------------------------------------
#define NB_BOT (256 * 512)
#define NB_COL (8192 * 16)

__device__ __forceinline__ int gkey(int idx, unsigned char m) {
    return (m & 2) ? idx : idx + NPIX;
}

__global__ void __launch_bounds__(256) k_union() {
    int t = blockIdx.x * 256 + threadIdx.x;
    if (t < NB_BOT) {
        int x = t & 511, ty = t >> 9;
        int y = ty * 32 + 31;
        if (y >= HH - 1) return;
        int idx = y * W + x;
        unsigned char mi = g_mask[idx];
        if (!(mi & 1)) return;
        int ki = gkey(idx, mi);
        int s = idx + W;
        unsigned char ms = g_mask[s];
        if (ms & 1) uf_union<NPIX>(g_nstat, ki, gkey(s, ms));
        if (x > 0) {
            unsigned char mw = g_mask[s - 1];
            if (mw & 1) uf_union<NPIX>(g_nstat, ki, gkey(s - 1, mw));
        }
        if (x < W - 1) {
            unsigned char me = g_mask[s + 1];
            if (me & 1) uf_union<NPIX>(g_nstat, ki, gkey(s + 1, me));
        }
    } else if (t < NB_BOT + NB_COL) {
        int t2 = t - NB_BOT;
        int y = t2 >> 4, tx = t2 & 15;
        int x = tx * 32 + 31;
        if (x >= W - 1) return;
        int idx = y * W + x;
        unsigned char mi = g_mask[idx];
        if (!(mi & 1)) return;
        int ki = gkey(idx, mi);
        unsigned char me = g_mask[idx + 1];
        if (me & 1) uf_union<NPIX>(g_nstat, ki, gkey(idx + 1, me));
        if ((y & 31) != 31 && y < HH - 1) {
            unsigned char md = g_mask[idx + W + 1];
            if (md & 1) uf_union<NPIX>(g_nstat, ki, gkey(idx + W + 1, md));
        }
    } else {
        int t3 = t - NB_BOT - NB_COL;
        if (t3 >= NB_COL) return;
        int y = t3 >> 4, tx = t3 & 15;
        int x = tx * 32;
        if (x == 0 || (y & 31) == 31 || y >= HH - 1) return;
        int idx = y * W + x;
        unsigned char mi = g_mask[idx];
        if (!(mi & 1)) return;
        unsigned char md = g_mask[idx + W - 1];
        if (md & 1) uf_union<NPIX>(g_nstat, gkey(idx, mi), gkey(idx + W - 1, md));
    }
}

// ---------------------------------------------------------------------------
// K3: find root per weak pixel; edge iff root key < NPIX (strong root)
// ---------------------------------------------------------------------------
__global__ void __launch_bounds__(256) k_out(float* __restrict__ out) {
    int t = blockIdx.x * 256 + threadIdx.x;
    int idx8 = t << 3;
    if (idx8 >= NPIX) return;
    uint2 m8 = *(const uint2*)(g_mask + idx8);
    unsigned int mw[2] = { m8.x, m8.y };
    unsigned int m[8];
    #pragma unroll
    for (int j = 0; j < 8; j++) m[j] = (mw[j >> 2] >> (8 * (j & 3))) & 0xFFu;

    // wave 1: independent first-hop parent loads (weak-only pixels)
    int par[8];
    #pragma unroll
    for (int j = 0; j < 8; j++)
        par[j] = (m[j] == 1u) ? g_nstat[idx8 + j] : -1;

    float v[8];
    #pragma unroll
    for (int j = 0; j < 8; j++) {
        float val = -1.0f;
        if (m[j] & 2u) {
            val = 1.0f;                         // strong => edge
        } else if (m[j] & 1u) {
            int idx = idx8 + j;
            int curr = par[j];
            int key = idx + NPIX;
            if (curr != key) {
                int prev = idx, next;
                while (curr > (next = g_nstat[curr & (NPIX - 1)])) {
                    g_nstat[prev] = next;       // halving: cooperate with peers
                    prev = curr & (NPIX - 1);
                    curr = next;
                }
            }
            if (curr < NPIX) val = 1.0f;        // strong-rooted component
        }
        v[j] = val;
    }

    int y = idx8 >> 9, x = idx8 & 511;
    int b = y >> 9, hh = y & 511;
    int o = ((b * 3) << 18) + (hh << 9) + x;
    float4 lo = make_float4(v[0], v[1], v[2], v[3]);
    float4 hi = make_float4(v[4], v[5], v[6], v[7]);
    float4* o4 = (float4*)out;
    int q = o >> 2;
    o4[q]             = lo;  o4[q + 1]             = hi;
    o4[q + (1 << 16)] = lo;  o4[q + (1 << 16) + 1] = hi;
    o4[q + (2 << 16)] = lo;  o4[q + (2 << 16) + 1] = hi;
}

extern "C" void kernel_launch(void* const* d_in, const int* in_sizes, int n_in,
                              void* d_out, int out_size) {
    const float* x = (const float*)d_in[0];
    float* out = (float*)d_out;
    dim3 g1(16, 256);
    k_grad<<<g1, 256>>>(x);
    k_union<<<(NB_BOT + 2 * NB_COL) / 256, 256>>>();
    k_out<<<NPIX / 2048, 256>>>(out);
}